// round 3
// baseline (speedup 1.0000x reference)
#include <cuda_runtime.h>
#include <cuda_bf16.h>

typedef unsigned long long ull;

#define TT 512
#define BBATCH 512
#define MROWS (TT * BBATCH)

// ---------------- packed f32x2 helpers (sm_103a dual-FP32 pipe) ----------------
__device__ __forceinline__ ull pk2(float lo, float hi) {
    ull r;
    asm("mov.b64 %0, {%1,%2};" : "=l"(r) : "f"(lo), "f"(hi));
    return r;
}
__device__ __forceinline__ void upk2(ull v, float& lo, float& hi) {
    asm("mov.b64 {%0,%1}, %2;" : "=f"(lo), "=f"(hi) : "l"(v));
}
__device__ __forceinline__ ull ffma2(ull a, ull b, ull c) {
    ull d;
    asm("fma.rn.f32x2 %0, %1, %2, %3;" : "=l"(d) : "l"(a), "l"(b), "l"(c));
    return d;
}

__device__ __forceinline__ float sigmf(float x) {
    return __fdividef(1.f, 1.f + __expf(-x));
}
__device__ __forceinline__ float tanh_fast(float x) {
    return 1.f - __fdividef(2.f, __expf(2.f * x) + 1.f);
}

// ---------------- scratch (device globals: no runtime allocation) ----------------
__device__ float g_xg[(size_t)TT * BBATCH * 400];   // reused per layer (max 4*H1)
__device__ float g_h1[(size_t)TT * BBATCH * 100];
__device__ float g_h2[(size_t)TT * BBATCH * 50];
__device__ float g_h3[(size_t)TT * BBATCH * 25];

// ---------------- input GEMM: C[M,N] = A[M,K] @ W[N,K]^T + b1 + b2 ----------------
#define BM 64
#define BN 64
#define BK 16
#define PITCH 68   // float4-aligned, low-conflict STS

template <bool K4>   // K4: K % 4 == 0 -> vectorized A/W loads
__global__ __launch_bounds__(256, 1)
void gemm_bias_kernel(const float* __restrict__ A,
                      const float* __restrict__ W,
                      const float* __restrict__ b1,
                      const float* __restrict__ b2,
                      float* __restrict__ C,
                      int M, int N, int K) {
    __shared__ float As[BK * PITCH];
    __shared__ float Ws[BK * PITCH];

    const int m0 = blockIdx.x * BM;
    const int n0 = blockIdx.y * BN;
    const int tid = threadIdx.x;
    const int tx = tid & 15;
    const int ty = tid >> 4;
    const int r = ty * 4;
    const int c = tx * 4;

    ull acc[2][4];
#pragma unroll
    for (int p = 0; p < 2; p++)
#pragma unroll
        for (int j = 0; j < 4; j++) acc[p][j] = 0ULL;

    const int ktiles = (K + BK - 1) / BK;
    for (int kt = 0; kt < ktiles; ++kt) {
        const int kbase = kt * BK;
        if (K4) {
            // 256 threads load 64 rows x 16 k: thread handles one row's 4-k chunk
            int rr = tid >> 2;            // 0..63
            int kk = (tid & 3) * 4;       // 0,4,8,12
            int kg = kbase + kk;
            float4 va = (kg + 3 < K)
                ? *reinterpret_cast<const float4*>(A + (size_t)(m0 + rr) * K + kg)
                : make_float4(0.f, 0.f, 0.f, 0.f);
            As[(kk + 0) * PITCH + rr] = va.x;
            As[(kk + 1) * PITCH + rr] = va.y;
            As[(kk + 2) * PITCH + rr] = va.z;
            As[(kk + 3) * PITCH + rr] = va.w;
            int cc = rr;
            float4 vw = (kg + 3 < K && (n0 + cc) < N)
                ? *reinterpret_cast<const float4*>(W + (size_t)(n0 + cc) * K + kg)
                : make_float4(0.f, 0.f, 0.f, 0.f);
            Ws[(kk + 0) * PITCH + cc] = vw.x;
            Ws[(kk + 1) * PITCH + cc] = vw.y;
            Ws[(kk + 2) * PITCH + cc] = vw.z;
            Ws[(kk + 3) * PITCH + cc] = vw.w;
        } else {
#pragma unroll
            for (int i = tid; i < BM * BK; i += 256) {
                int rr = i >> 4;          // i / BK
                int kk = i & 15;          // i % BK
                int kg = kbase + kk;
                float va = (kg < K) ? A[(size_t)(m0 + rr) * K + kg] : 0.f;
                As[kk * PITCH + rr] = va;
                int cc = rr;
                float vw = (kg < K && (n0 + cc) < N) ? W[(size_t)(n0 + cc) * K + kg] : 0.f;
                Ws[kk * PITCH + cc] = vw;
            }
        }
        __syncthreads();

#pragma unroll
        for (int k = 0; k < BK; ++k) {
            ull a01 = *reinterpret_cast<const ull*>(As + k * PITCH + r);
            ull a23 = *reinterpret_cast<const ull*>(As + k * PITCH + r + 2);
            float4 bv = *reinterpret_cast<const float4*>(Ws + k * PITCH + c);
            ull bd0 = pk2(bv.x, bv.x);
            ull bd1 = pk2(bv.y, bv.y);
            ull bd2 = pk2(bv.z, bv.z);
            ull bd3 = pk2(bv.w, bv.w);
            acc[0][0] = ffma2(a01, bd0, acc[0][0]);
            acc[1][0] = ffma2(a23, bd0, acc[1][0]);
            acc[0][1] = ffma2(a01, bd1, acc[0][1]);
            acc[1][1] = ffma2(a23, bd1, acc[1][1]);
            acc[0][2] = ffma2(a01, bd2, acc[0][2]);
            acc[1][2] = ffma2(a23, bd2, acc[1][2]);
            acc[0][3] = ffma2(a01, bd3, acc[0][3]);
            acc[1][3] = ffma2(a23, bd3, acc[1][3]);
        }
        __syncthreads();
    }

#pragma unroll
    for (int j = 0; j < 4; ++j) {
        int col = n0 + c + j;
        if (col < N) {
            float bias = __ldg(b1 + col) + __ldg(b2 + col);
            float v0, v1, v2, v3;
            upk2(acc[0][j], v0, v1);
            upk2(acc[1][j], v2, v3);
            size_t base = (size_t)(m0 + r) * N + col;
            C[base]                 = v0 + bias;
            C[base + N]             = v1 + bias;
            C[base + 2 * (size_t)N] = v2 + bias;
            C[base + 3 * (size_t)N] = v3 + bias;
        }
    }
}

// ---------------- recurrent LSTM scan, one layer ----------------
// Grid: B/4 blocks; each block owns 4 batch columns for all T steps.
// GPT = gates per thread (1 or 2). NT = 4H/GPT threads.
//   GPT=2: thread t computes adjacent gate rows (2t, 2t+1) -> LDS.64 weight pair.
//   GPT=1: thread t computes gate row t.
// Activation phase: spread over all NT threads; each handles (h = tid%H) for
// BPT = GPT consecutive batches starting at (tid/H)*GPT.
template <int H, int GPT>
__global__ __launch_bounds__(4 * H / GPT, 1)
void lstm_rec_kernel(const float* __restrict__ xg,
                     const float* __restrict__ whh,
                     float* __restrict__ hs) {
    constexpr int FH = 4 * H;
    constexpr int NT = FH / GPT;
    constexpr int BPT = GPT;                 // batches per activation thread
    extern __shared__ float sm[];
    float* wsm  = sm;                // [H][FH]  (transposed w_hh)
    float* hsm  = sm + H * FH;       // [H][4]   (h state, batch-fastest)
    float* gbuf = hsm + 4 * H;       // [4][FH]  (gate preactivations)

    const int tid = threadIdx.x;
    const int b0 = blockIdx.x * 4;

    // load weights transposed: wsm[k][j] = whh[j][k]
    for (int i = tid; i < FH * H; i += NT) {
        int j = i / H;
        int k = i - j * H;
        wsm[k * FH + j] = whh[i];
    }
    for (int i = tid; i < 4 * H; i += NT) hsm[i] = 0.f;

    const int ah  = tid % H;             // activation h-index
    const int ab0 = (tid / H) * BPT;     // activation batch base
    float cst[BPT];
#pragma unroll
    for (int b = 0; b < BPT; ++b) cst[b] = 0.f;
    __syncthreads();

    if (GPT == 2) {
        const int j0 = 2 * tid;          // adjacent gate pair
        float nx[8];                     // [batch0..3] x {j0, j1}
        {
            size_t bb = (size_t)b0 * FH + j0;
#pragma unroll
            for (int b = 0; b < 4; ++b) {
                float2 v = *reinterpret_cast<const float2*>(xg + bb + (size_t)b * FH);
                nx[2 * b] = v.x; nx[2 * b + 1] = v.y;
            }
        }

        for (int t = 0; t < TT; ++t) {
            ull aA01 = pk2(nx[0], nx[2]);   // gate j0, batches 0,1
            ull aA23 = pk2(nx[4], nx[6]);   // gate j0, batches 2,3
            ull aB01 = pk2(nx[1], nx[3]);   // gate j1, batches 0,1
            ull aB23 = pk2(nx[5], nx[7]);   // gate j1, batches 2,3

            if (t + 1 < TT) {  // prefetch next step's xg (hides DRAM latency)
                size_t bb = ((size_t)(t + 1) * BBATCH + b0) * FH + j0;
#pragma unroll
                for (int b = 0; b < 4; ++b) {
                    float2 v = *reinterpret_cast<const float2*>(xg + bb + (size_t)b * FH);
                    nx[2 * b] = v.x; nx[2 * b + 1] = v.y;
                }
            }

#pragma unroll 5
            for (int k = 0; k < H; ++k) {
                float2 w2 = *reinterpret_cast<const float2*>(wsm + k * FH + j0);
                ulonglong2 hv = *reinterpret_cast<const ulonglong2*>(hsm + k * 4);
                ull wa2 = pk2(w2.x, w2.x);
                ull wb2 = pk2(w2.y, w2.y);
                aA01 = ffma2(wa2, hv.x, aA01);
                aA23 = ffma2(wa2, hv.y, aA23);
                aB01 = ffma2(wb2, hv.x, aB01);
                aB23 = ffma2(wb2, hv.y, aB23);
            }

            float v0, v1;
            upk2(aA01, v0, v1); gbuf[0 * FH + j0] = v0; gbuf[1 * FH + j0] = v1;
            upk2(aA23, v0, v1); gbuf[2 * FH + j0] = v0; gbuf[3 * FH + j0] = v1;
            upk2(aB01, v0, v1); gbuf[0 * FH + j0 + 1] = v0; gbuf[1 * FH + j0 + 1] = v1;
            upk2(aB23, v0, v1); gbuf[2 * FH + j0 + 1] = v0; gbuf[3 * FH + j0 + 1] = v1;
            __syncthreads();

#pragma unroll
            for (int b = 0; b < BPT; ++b) {
                const float* gb = gbuf + (ab0 + b) * FH;
                float gi = gb[ah];
                float gf = gb[H + ah];
                float gg = gb[2 * H + ah];
                float go = gb[3 * H + ah];
                float cc = sigmf(gf) * cst[b] + sigmf(gi) * tanh_fast(gg);
                cst[b] = cc;
                float h = sigmf(go) * tanh_fast(cc);
                hsm[ah * 4 + (ab0 + b)] = h;
                hs[((size_t)t * BBATCH + b0 + ab0 + b) * H + ah] = h;
            }
            __syncthreads();
        }
    } else {
        const int j = tid;
        float nx[4];
        {
            size_t bb = (size_t)b0 * FH + j;
#pragma unroll
            for (int b = 0; b < 4; ++b) nx[b] = xg[bb + (size_t)b * FH];
        }

        for (int t = 0; t < TT; ++t) {
            ull a01 = pk2(nx[0], nx[1]);
            ull a23 = pk2(nx[2], nx[3]);

            if (t + 1 < TT) {
                size_t bb = ((size_t)(t + 1) * BBATCH + b0) * FH + j;
#pragma unroll
                for (int b = 0; b < 4; ++b) nx[b] = xg[bb + (size_t)b * FH];
            }

#pragma unroll 5
            for (int k = 0; k < H; ++k) {
                float w = wsm[k * FH + j];
                ulonglong2 hv = *reinterpret_cast<const ulonglong2*>(hsm + k * 4);
                ull w2 = pk2(w, w);
                a01 = ffma2(w2, hv.x, a01);
                a23 = ffma2(w2, hv.y, a23);
            }

            float v0, v1;
            upk2(a01, v0, v1); gbuf[0 * FH + j] = v0; gbuf[1 * FH + j] = v1;
            upk2(a23, v0, v1); gbuf[2 * FH + j] = v0; gbuf[3 * FH + j] = v1;
            __syncthreads();

            {
                const float* gb = gbuf + ab0 * FH;
                float gi = gb[ah];
                float gf = gb[H + ah];
                float gg = gb[2 * H + ah];
                float go = gb[3 * H + ah];
                float cc = sigmf(gf) * cst[0] + sigmf(gi) * tanh_fast(gg);
                cst[0] = cc;
                float h = sigmf(go) * tanh_fast(cc);
                hsm[ah * 4 + ab0] = h;
                hs[((size_t)t * BBATCH + b0 + ab0) * H + ah] = h;
            }
            __syncthreads();
        }
    }
}

// ---------------- final linear: out[m] = h3[m,:25] . w + b ----------------
__global__ __launch_bounds__(256)
void linear_kernel(const float* __restrict__ h3,
                   const float* __restrict__ w,
                   const float* __restrict__ b,
                   float* __restrict__ out, int M) {
    __shared__ float ws[32];
    if (threadIdx.x < 25) ws[threadIdx.x] = w[threadIdx.x];
    __syncthreads();
    int m = blockIdx.x * blockDim.x + threadIdx.x;
    if (m < M) {
        float acc = b[0];
        const float* hp = h3 + (size_t)m * 25;
#pragma unroll
        for (int k = 0; k < 25; ++k) acc += hp[k] * ws[k];
        out[m] = acc;
    }
}

// ---------------- launch ----------------
extern "C" void kernel_launch(void* const* d_in, const int* in_sizes, int n_in,
                              void* d_out, int out_size) {
    const float* x     = (const float*)d_in[0];
    const float* w_ih1 = (const float*)d_in[1];
    const float* w_hh1 = (const float*)d_in[2];
    const float* b_ih1 = (const float*)d_in[3];
    const float* b_hh1 = (const float*)d_in[4];
    const float* w_ih2 = (const float*)d_in[5];
    const float* w_hh2 = (const float*)d_in[6];
    const float* b_ih2 = (const float*)d_in[7];
    const float* b_hh2 = (const float*)d_in[8];
    const float* w_ih3 = (const float*)d_in[9];
    const float* w_hh3 = (const float*)d_in[10];
    const float* b_ih3 = (const float*)d_in[11];
    const float* b_hh3 = (const float*)d_in[12];
    const float* w_lin = (const float*)d_in[13];
    const float* b_lin = (const float*)d_in[14];
    float* out = (float*)d_out;

    float *xg, *h1, *h2, *h3;
    cudaGetSymbolAddress((void**)&xg, g_xg);
    cudaGetSymbolAddress((void**)&h1, g_h1);
    cudaGetSymbolAddress((void**)&h2, g_h2);
    cudaGetSymbolAddress((void**)&h3, g_h3);

    const int smem1 = (4 * 100 * 100 + 20 * 100) * 4;  // 168000 B
    const int smem2 = (4 * 50 * 50 + 20 * 50) * 4;     //  44000 B
    const int smem3 = (4 * 25 * 25 + 20 * 25) * 4;     //  12000 B
    cudaFuncSetAttribute((const void*)lstm_rec_kernel<100, 2>,
                         cudaFuncAttributeMaxDynamicSharedMemorySize, smem1);
    cudaFuncSetAttribute((const void*)lstm_rec_kernel<50, 1>,
                         cudaFuncAttributeMaxDynamicSharedMemorySize, smem2);
    cudaFuncSetAttribute((const void*)lstm_rec_kernel<25, 1>,
                         cudaFuncAttributeMaxDynamicSharedMemorySize, smem3);

    const int M = MROWS;

    // Layer 1 (K=64: vectorized loads)
    gemm_bias_kernel<true><<<dim3(M / BM, (400 + BN - 1) / BN), 256>>>(x, w_ih1, b_ih1, b_hh1, xg, M, 400, 64);
    lstm_rec_kernel<100, 2><<<BBATCH / 4, 200, smem1>>>(xg, w_hh1, h1);
    // Layer 2 (K=100: vectorized loads)
    gemm_bias_kernel<true><<<dim3(M / BM, (200 + BN - 1) / BN), 256>>>(h1, w_ih2, b_ih2, b_hh2, xg, M, 200, 100);
    lstm_rec_kernel<50, 1><<<BBATCH / 4, 200, smem2>>>(xg, w_hh2, h2);
    // Layer 3 (K=50: scalar loads)
    gemm_bias_kernel<false><<<dim3(M / BM, (100 + BN - 1) / BN), 256>>>(h2, w_ih3, b_ih3, b_hh3, xg, M, 100, 50);
    lstm_rec_kernel<25, 1><<<BBATCH / 4, 100, smem3>>>(xg, w_hh3, h3);
    // Output projection
    linear_kernel<<<(M + 255) / 256, 256>>>(h3, w_lin, b_lin, out, M);
}